// round 1
// baseline (speedup 1.0000x reference)
#include <cuda_runtime.h>
#include <cfloat>

#define NB     2048
#define ND     1024
#define NH     2048
#define NEXP   8
#define NSEQ   128
#define NC     10
#define NSTEPS 5
#define LNEPS  1e-5f

// ---------------- device-global scratch (no cudaMalloc allowed) ----------------
__device__ float g_h[NB * ND];        // pooled / evolving hidden state (8 MB)
__device__ float g_hidden[NB * ND];   // router hidden, compacted by active list (8 MB)
__device__ float g_z1[NB * NH];       // expert layer-1 output, indexed by sample (16 MB)
__device__ float g_z2[NB * ND];       // expert layer-2 output, indexed by sample (8 MB)
__device__ int   g_listA[NB];
__device__ int   g_listB[NB];
__device__ int   g_elist[NEXP * NB];  // per-expert sample lists (stride NB)
__device__ int   g_actsel[NB];        // chosen expert per sample
__device__ int   g_cnt[16];           // [0]=cntA [1]=cntB [8..15]=per-expert counts

// ---------------- init ----------------
__global__ void init_kernel(int* list, int* cnt) {
    int i = blockIdx.x * blockDim.x + threadIdx.x;
    if (i < NB) list[i] = i;
    if (i == 0) cnt[0] = NB;
}

__global__ void reset_kernel(int* nxtCnt, int* expertCnt) {
    if (threadIdx.x == 0) *nxtCnt = 0;
    if (threadIdx.x < NEXP) expertCnt[threadIdx.x] = 0;
}

// ---------------- embedding + masked mean pool ----------------
__global__ __launch_bounds__(256) void embed_kernel(
    const int* __restrict__ ids, const float* __restrict__ emb,
    float* __restrict__ h)
{
    int b = blockIdx.x, tid = threadIdx.x;
    __shared__ int sid[NSEQ];
    if (tid < NSEQ) sid[tid] = ids[b * NSEQ + tid];
    __syncthreads();

    float4 acc = make_float4(0.f, 0.f, 0.f, 0.f);
    int cnt = 0;
    for (int s = 0; s < NSEQ; ++s) {
        int id = sid[s];
        if (id != 0) {  // PAD = 0
            ++cnt;
            float4 v = *(const float4*)&emb[(size_t)id * ND + tid * 4];
            acc.x += v.x; acc.y += v.y; acc.z += v.z; acc.w += v.w;
        }
    }
    float inv = 1.f / (float)(cnt > 0 ? cnt : 1);
    acc.x *= inv; acc.y *= inv; acc.z *= inv; acc.w *= inv;
    *(float4*)&h[(size_t)b * ND + tid * 4] = acc;
}

// ---------------- generic gathered/scattered fp32 SGEMM ----------------
// C[out] = (relu?)(A[rows] @ W + bias). 128x128 tile, BK=16, 256 threads, 8x8/thread.
// grid: (mtiles, N/128, nGroups). Per-group: rows += z*rowStride, W += z*wStride,
// bias += z*bStride, M = cnts[z]. scatter ? out row = rows[r] : compact row r.
__global__ __launch_bounds__(256) void sgemm_kernel(
    const float* __restrict__ A, const float* __restrict__ W,
    const float* __restrict__ bias, float* __restrict__ Cout,
    const int* __restrict__ rows, const int* __restrict__ cnts,
    int K, int N, int doRelu, int scatter,
    size_t wStride, int bStride, int rowStride)
{
    int e = blockIdx.z;
    int M = cnts[e];
    int mBase = blockIdx.x * 128;
    if (mBase >= M) return;
    int nBase = blockIdx.y * 128;

    const int*   rowsE = rows + (size_t)e * rowStride;
    const float* We    = W    + (size_t)e * wStride;
    const float* biasE = bias + (size_t)e * bStride;

    __shared__ float As[16][128];
    __shared__ float Bs[16][128];

    int tid = threadIdx.x;
    int tx = tid & 15, ty = tid >> 4;

    // A-tile loader: 128 rows x 16 k; thread loads 2 float4s
    int lrow = tid >> 2;          // 0..63
    int lk4  = (tid & 3) * 4;     // 0,4,8,12
    int gm0 = mBase + lrow, gm1 = mBase + lrow + 64;
    const float* aP0 = nullptr; const float* aP1 = nullptr;
    if (gm0 < M) aP0 = A + (size_t)rowsE[gm0] * K + lk4;
    if (gm1 < M) aP1 = A + (size_t)rowsE[gm1] * K + lk4;

    // B-tile loader: 16 k x 128 n; thread loads 2 float4s
    int lkb = tid >> 5;           // 0..7
    int ln4 = (tid & 31) * 4;     // 0..124
    const float* bP = We + (size_t)lkb * N + nBase + ln4;

    float acc[8][8];
#pragma unroll
    for (int i = 0; i < 8; ++i)
#pragma unroll
        for (int j = 0; j < 8; ++j) acc[i][j] = 0.f;

    for (int k0 = 0; k0 < K; k0 += 16) {
        float4 va0 = make_float4(0.f,0.f,0.f,0.f), va1 = make_float4(0.f,0.f,0.f,0.f);
        if (aP0) va0 = *(const float4*)(aP0 + k0);
        if (aP1) va1 = *(const float4*)(aP1 + k0);
        float4 vb0 = *(const float4*)(bP + (size_t)k0 * N);
        float4 vb1 = *(const float4*)(bP + (size_t)(k0 + 8) * N);

        __syncthreads();  // previous tile's compute done
        As[lk4 + 0][lrow] = va0.x; As[lk4 + 1][lrow] = va0.y;
        As[lk4 + 2][lrow] = va0.z; As[lk4 + 3][lrow] = va0.w;
        As[lk4 + 0][lrow + 64] = va1.x; As[lk4 + 1][lrow + 64] = va1.y;
        As[lk4 + 2][lrow + 64] = va1.z; As[lk4 + 3][lrow + 64] = va1.w;
        *(float4*)&Bs[lkb][ln4]     = vb0;
        *(float4*)&Bs[lkb + 8][ln4] = vb1;
        __syncthreads();

#pragma unroll
        for (int kk = 0; kk < 16; ++kk) {
            float a[8], b[8];
            *(float4*)&a[0] = *(const float4*)&As[kk][ty * 8];
            *(float4*)&a[4] = *(const float4*)&As[kk][ty * 8 + 4];
            *(float4*)&b[0] = *(const float4*)&Bs[kk][tx * 8];
            *(float4*)&b[4] = *(const float4*)&Bs[kk][tx * 8 + 4];
#pragma unroll
            for (int i = 0; i < 8; ++i)
#pragma unroll
                for (int j = 0; j < 8; ++j) acc[i][j] += a[i] * b[j];
        }
    }

    float bb[8];
#pragma unroll
    for (int j = 0; j < 8; ++j) bb[j] = biasE[nBase + tx * 8 + j];

#pragma unroll
    for (int i = 0; i < 8; ++i) {
        int r = mBase + ty * 8 + i;
        if (r >= M) break;
        int orow = scatter ? rowsE[r] : r;
        float v[8];
#pragma unroll
        for (int j = 0; j < 8; ++j) {
            float x = acc[i][j] + bb[j];
            v[j] = doRelu ? fmaxf(x, 0.f) : x;
        }
        float* op = Cout + (size_t)orow * N + nBase + tx * 8;
        *(float4*)op       = make_float4(v[0], v[1], v[2], v[3]);
        *(float4*)(op + 4) = make_float4(v[4], v[5], v[6], v[7]);
    }
}

// ---------------- router logits + argmax + dispatch/compaction ----------------
__global__ __launch_bounds__(128) void dispatch_kernel(
    const float* __restrict__ hidden, const float* __restrict__ W2,
    const float* __restrict__ b2,
    const int* __restrict__ curList, const int* __restrict__ curCnt,
    int* __restrict__ nextList, int* __restrict__ nextCnt,
    int* __restrict__ expertList, int* __restrict__ expertCnt,
    int* __restrict__ actOut)
{
    int i = blockIdx.x;
    if (i >= *curCnt) return;
    int tid = threadIdx.x;

    __shared__ float sW2[ND * (NEXP + 1)];   // 36 KB
    __shared__ float sred[4][NEXP + 1];
    for (int idx = tid; idx < ND * (NEXP + 1); idx += 128) sW2[idx] = W2[idx];
    __syncthreads();

    float acc[NEXP + 1];
#pragma unroll
    for (int j = 0; j <= NEXP; ++j) acc[j] = 0.f;

    const float* hr = hidden + (size_t)i * ND;
    for (int k = tid; k < ND; k += 128) {
        float hv = hr[k];
#pragma unroll
        for (int j = 0; j <= NEXP; ++j) acc[j] += hv * sW2[k * (NEXP + 1) + j];
    }
#pragma unroll
    for (int j = 0; j <= NEXP; ++j)
        for (int o = 16; o; o >>= 1) acc[j] += __shfl_xor_sync(0xffffffffu, acc[j], o);
    int warp = tid >> 5, lane = tid & 31;
    if (lane == 0)
#pragma unroll
        for (int j = 0; j <= NEXP; ++j) sred[warp][j] = acc[j];
    __syncthreads();

    if (tid == 0) {
        float best = -FLT_MAX; int bi = 0;
#pragma unroll
        for (int j = 0; j <= NEXP; ++j) {
            float v = sred[0][j] + sred[1][j] + sred[2][j] + sred[3][j] + b2[j];
            if (v > best) { best = v; bi = j; }   // strict > : first-max tie-break (jnp.argmax)
        }
        if (bi < NEXP) {                           // continue: dispatch to expert bi
            int sample = curList[i];
            int p = atomicAdd(&expertCnt[bi], 1);
            expertList[bi * NB + p] = sample;
            int q = atomicAdd(nextCnt, 1);
            nextList[q] = sample;
            actOut[sample] = bi;
        }
        // bi == NEXP: terminate. h is frozen from now on; "final" == h.
    }
}

// ---------------- LayerNorm + residual into h ----------------
__global__ __launch_bounds__(256) void ln_kernel(
    const float* __restrict__ z2, float* __restrict__ h,
    const float* __restrict__ g, const float* __restrict__ beta,
    const int* __restrict__ nextList, const int* __restrict__ nextCnt,
    const int* __restrict__ actSel)
{
    int j = blockIdx.x;
    if (j >= *nextCnt) return;
    int sample = nextList[j];
    int e = actSel[sample];
    int tid = threadIdx.x;

    const float4 x = *(const float4*)&z2[(size_t)sample * ND + tid * 4];

    __shared__ float red[8];
    __shared__ float bc;
    int warp = tid >> 5, lane = tid & 31;

    float s = x.x + x.y + x.z + x.w;
    for (int o = 16; o; o >>= 1) s += __shfl_xor_sync(0xffffffffu, s, o);
    if (lane == 0) red[warp] = s;
    __syncthreads();
    if (tid == 0) {
        float t = 0.f;
        for (int w = 0; w < 8; ++w) t += red[w];
        bc = t * (1.f / ND);
    }
    __syncthreads();
    float mean = bc;
    __syncthreads();   // everyone read mean before bc is reused

    float d0 = x.x - mean, d1 = x.y - mean, d2 = x.z - mean, d3 = x.w - mean;
    float ss = d0 * d0 + d1 * d1 + d2 * d2 + d3 * d3;
    for (int o = 16; o; o >>= 1) ss += __shfl_xor_sync(0xffffffffu, ss, o);
    if (lane == 0) red[warp] = ss;
    __syncthreads();
    if (tid == 0) {
        float t = 0.f;
        for (int w = 0; w < 8; ++w) t += red[w];
        bc = t * (1.f / ND);
    }
    __syncthreads();
    float rstd = rsqrtf(bc + LNEPS);

    float4 hv = *(const float4*)&h[(size_t)sample * ND + tid * 4];
    float4 gg = *(const float4*)&g[(size_t)e * ND + tid * 4];
    float4 bt = *(const float4*)&beta[(size_t)e * ND + tid * 4];
    float4 o;
    o.x = hv.x + d0 * rstd * gg.x + bt.x;
    o.y = hv.y + d1 * rstd * gg.y + bt.y;
    o.z = hv.z + d2 * rstd * gg.z + bt.z;
    o.w = hv.w + d3 * rstd * gg.w + bt.w;
    *(float4*)&h[(size_t)sample * ND + tid * 4] = o;
}

// ---------------- output head ----------------
__global__ __launch_bounds__(256) void head_kernel(
    const float* __restrict__ h, const float* __restrict__ oW,
    const float* __restrict__ ob, float* __restrict__ out)
{
    int b = blockIdx.x, tid = threadIdx.x;
    float acc[NC];
#pragma unroll
    for (int j = 0; j < NC; ++j) acc[j] = 0.f;

    const float* hr = h + (size_t)b * ND;
    for (int k = tid; k < ND; k += 256) {
        float hv = hr[k];
#pragma unroll
        for (int j = 0; j < NC; ++j) acc[j] += hv * oW[k * NC + j];
    }
#pragma unroll
    for (int j = 0; j < NC; ++j)
        for (int o = 16; o; o >>= 1) acc[j] += __shfl_xor_sync(0xffffffffu, acc[j], o);

    __shared__ float sred[8][NC];
    int warp = tid >> 5, lane = tid & 31;
    if (lane == 0)
#pragma unroll
        for (int j = 0; j < NC; ++j) sred[warp][j] = acc[j];
    __syncthreads();
    if (tid < NC) {
        float t = 0.f;
        for (int w = 0; w < 8; ++w) t += sred[w][tid];
        out[b * NC + tid] = t + ob[tid];
    }
}

// ---------------- launch ----------------
extern "C" void kernel_launch(void* const* d_in, const int* in_sizes, int n_in,
                              void* d_out, int out_size)
{
    const int*   ids = (const int*)d_in[0];
    const float* emb = (const float*)d_in[1];
    const float* rW1 = (const float*)d_in[2];
    const float* rb1 = (const float*)d_in[3];
    const float* rW2 = (const float*)d_in[4];
    const float* rb2 = (const float*)d_in[5];
    const float* eW1 = (const float*)d_in[6];
    const float* eb1 = (const float*)d_in[7];
    const float* eW2 = (const float*)d_in[8];
    const float* eb2 = (const float*)d_in[9];
    const float* eg  = (const float*)d_in[10];
    const float* ebt = (const float*)d_in[11];
    const float* oW  = (const float*)d_in[12];
    const float* ob  = (const float*)d_in[13];
    float* out = (float*)d_out;

    void *p; 
    cudaGetSymbolAddress(&p, g_h);      float* h      = (float*)p;
    cudaGetSymbolAddress(&p, g_hidden); float* hidden = (float*)p;
    cudaGetSymbolAddress(&p, g_z1);     float* z1     = (float*)p;
    cudaGetSymbolAddress(&p, g_z2);     float* z2     = (float*)p;
    cudaGetSymbolAddress(&p, g_listA);  int* listA    = (int*)p;
    cudaGetSymbolAddress(&p, g_listB);  int* listB    = (int*)p;
    cudaGetSymbolAddress(&p, g_elist);  int* elist    = (int*)p;
    cudaGetSymbolAddress(&p, g_actsel); int* actsel   = (int*)p;
    cudaGetSymbolAddress(&p, g_cnt);    int* cnt      = (int*)p;

    init_kernel<<<8, 256>>>(listA, cnt);
    embed_kernel<<<NB, 256>>>(ids, emb, h);

    for (int step = 0; step < NSTEPS; ++step) {
        int* curList = (step & 1) ? listB : listA;
        int* nxtList = (step & 1) ? listA : listB;
        int* curCnt  = cnt + (step & 1);
        int* nxtCnt  = cnt + ((step + 1) & 1);
        int* eCnt    = cnt + 8;

        reset_kernel<<<1, 32>>>(nxtCnt, eCnt);

        // router layer 1: hidden = relu(h[cur] @ rW1 + rb1), compacted rows
        {
            dim3 grid(NB / 128, ND / 128, 1);
            sgemm_kernel<<<grid, 256>>>(h, rW1, rb1, hidden, curList, curCnt,
                                        ND, ND, 1, 0, (size_t)0, 0, 0);
        }
        // router layer 2 + argmax + compaction
        dispatch_kernel<<<NB, 128>>>(hidden, rW2, rb2, curList, curCnt,
                                     nxtList, nxtCnt, elist, eCnt, actsel);
        // expert layer 1: z1[sample] = relu(h[sample] @ eW1[e] + eb1[e])
        {
            dim3 grid(NB / 128, NH / 128, NEXP);
            sgemm_kernel<<<grid, 256>>>(h, eW1, eb1, z1, elist, eCnt,
                                        ND, NH, 1, 1, (size_t)ND * NH, NH, NB);
        }
        // expert layer 2: z2[sample] = z1[sample] @ eW2[e] + eb2[e]
        {
            dim3 grid(NB / 128, ND / 128, NEXP);
            sgemm_kernel<<<grid, 256>>>(z1, eW2, eb2, z2, elist, eCnt,
                                        NH, ND, 0, 1, (size_t)NH * ND, ND, NB);
        }
        // h[sample] += LN(z2[sample]) * g[e] + beta[e]
        ln_kernel<<<NB, 256>>>(z2, h, eg, ebt, nxtList, nxtCnt, actsel);
    }

    head_kernel<<<NB, 256>>>(h, oW, ob, out);
}

// round 6
// speedup vs baseline: 2.2237x; 2.2237x over previous
#include <cuda_runtime.h>
#include <cuda_fp16.h>
#include <cfloat>
#include <cstdint>

#define NB     2048
#define ND     1024
#define NH     2048
#define NEXP   8
#define NSEQ   128
#define NC     10
#define NSTEPS 5
#define LNEPS  1e-5f
#define MIDSC  2048.0f
#define IMIDSC (1.0f/2048.0f)

// ================= device-global scratch (no cudaMalloc allowed) =================
__device__ float g_h[NB * ND];
__device__ float g_hidden[NB * ND];
__device__ float g_z1[NB * NH];
__device__ float g_z2[NB * ND];
__device__ int   g_listA[NB];
__device__ int   g_listB[NB];
__device__ int   g_elist[NEXP * NB];
__device__ int   g_actsel[NB];
__device__ int   g_cnt[16];

// fp16 split weight buffers: for each weight, [N,K] transposed, hi then mid(x2048)
#define S_RW1  (ND * ND)
#define S_EW1  (NEXP * ND * NH)
#define S_EW2  (NEXP * NH * ND)
#define WB_RW1 0
#define WB_EW1 (2 * S_RW1)
#define WB_EW2 (WB_EW1 + 2 * S_EW1)
#define WB_TOT (WB_EW2 + 2 * S_EW2)
__device__ __half g_wbuf[WB_TOT];

// ================= helpers =================
__device__ __forceinline__ uint32_t smem_u32(const void* p) {
    uint32_t a;
    asm("{ .reg .u64 t; cvta.to.shared.u64 t, %1; cvt.u32.u64 %0, t; }" : "=r"(a) : "l"(p));
    return a;
}
#define LDSM_X4(r0, r1, r2, r3, addr) \
    asm volatile("ldmatrix.sync.aligned.m8n8.x4.shared.b16 {%0,%1,%2,%3}, [%4];" \
        : "=r"(r0), "=r"(r1), "=r"(r2), "=r"(r3) : "r"(addr))
#define MMA16816(d, a, b) \
    asm volatile("mma.sync.aligned.m16n8k16.row.col.f32.f16.f16.f32 " \
        "{%0,%1,%2,%3}, {%4,%5,%6,%7}, {%8,%9}, {%0,%1,%2,%3};" \
        : "+f"((d)[0]), "+f"((d)[1]), "+f"((d)[2]), "+f"((d)[3]) \
        : "r"((a)[0]), "r"((a)[1]), "r"((a)[2]), "r"((a)[3]), "r"((b)[0]), "r"((b)[1]))

__device__ __forceinline__ void split2(float x, __half& hi, __half& md) {
    hi = __float2half_rn(x);
    float r = x - __half2float(hi);
    md = __float2half_rn(r * MIDSC);
}
__device__ __forceinline__ uint32_t packh(__half a, __half b) {
    __half2 p; p.x = a; p.y = b;
    return *reinterpret_cast<uint32_t*>(&p);
}

// ================= init =================
__global__ void init_kernel(int* list, int* cnt) {
    int i = blockIdx.x * blockDim.x + threadIdx.x;
    if (i < NB) list[i] = i;
    if (i == 0) cnt[0] = NB;
}
__global__ void reset_kernel(int* nxtCnt, int* expertCnt) {
    if (threadIdx.x == 0) *nxtCnt = 0;
    if (threadIdx.x < NEXP) expertCnt[threadIdx.x] = 0;
}

// ===== weight transpose+split: W[K,N] fp32 -> Wt[N,K] fp16 hi / mid(x2048) =====
__global__ __launch_bounds__(256) void convT_kernel(
    const float* __restrict__ W, __half* __restrict__ hi, __half* __restrict__ md,
    int K, int N)
{
    int g = blockIdx.z;
    size_t base = (size_t)g * K * N;
    __shared__ float t[32][33];
    int n0 = blockIdx.x * 32, k0 = blockIdx.y * 32;
    int tx = threadIdx.x, ty = threadIdx.y;
#pragma unroll
    for (int r = ty; r < 32; r += 8)
        t[r][tx] = W[base + (size_t)(k0 + r) * N + n0 + tx];
    __syncthreads();
#pragma unroll
    for (int r = ty; r < 32; r += 8) {
        float x = t[tx][r];
        __half h, m;
        split2(x, h, m);
        size_t oi = base + (size_t)(n0 + r) * K + k0 + tx;
        hi[oi] = h; md[oi] = m;
    }
}

// ================= embedding + masked mean pool =================
__global__ __launch_bounds__(256) void embed_kernel(
    const int* __restrict__ ids, const float* __restrict__ emb,
    float* __restrict__ h)
{
    int b = blockIdx.x, tid = threadIdx.x;
    __shared__ int sid[NSEQ];
    if (tid < NSEQ) sid[tid] = ids[b * NSEQ + tid];
    __syncthreads();

    float4 acc = make_float4(0.f, 0.f, 0.f, 0.f);
    int cnt = 0;
    for (int s = 0; s < NSEQ; ++s) {
        int id = sid[s];
        if (id != 0) {
            ++cnt;
            float4 v = *(const float4*)&emb[(size_t)id * ND + tid * 4];
            acc.x += v.x; acc.y += v.y; acc.z += v.z; acc.w += v.w;
        }
    }
    float inv = 1.f / (float)(cnt > 0 ? cnt : 1);
    acc.x *= inv; acc.y *= inv; acc.z *= inv; acc.w *= inv;
    *(float4*)&h[(size_t)b * ND + tid * 4] = acc;
}

// ============ HMMA fp16x2-split gathered/scattered GEMM ============
// C[out] = (relu?)(A[rows] @ Wt^T + bias). A fp32 gathered + split inline,
// Wt pre-split fp16 hi/mid [N,K]. Tile 128x128, BK=32, 256 thr, 8 warps (64x32).
// smem: [0,512) srows; stage s at 1024 + s*32768:
//   Ahi +0, Amid +8192, Bhi +16384, Bmid +24576  (each 128 rows x 64B, XOR swizz)
#define STG_BASE 1024
#define STG_SZ   32768
#define HG_SMEM  (STG_BASE + 2 * STG_SZ)

__global__ __launch_bounds__(256) void hmma_gemm_kernel(
    const float* __restrict__ A,
    const __half* __restrict__ Whi, const __half* __restrict__ Wmd,
    const float* __restrict__ bias, float* __restrict__ Cout,
    const int* __restrict__ rows, const int* __restrict__ cnts,
    int K, int N, int doRelu, int scatter,
    size_t wStride, int bStride, int rowStride)
{
    extern __shared__ char smem[];
    int e = blockIdx.z;
    int M = cnts[e];
    int mBase = blockIdx.x * 128;
    if (mBase >= M) return;
    int nBase = blockIdx.y * 128;
    int tid = threadIdx.x, wid = tid >> 5, lane = tid & 31;

    uint32_t sb = smem_u32(smem);
    int* srows = (int*)smem;
    if (tid < 128) {
        int gm = mBase + tid; if (gm >= M) gm = M - 1;
        srows[tid] = rows[(size_t)e * rowStride + gm];
    }
    __syncthreads();

    // loader: thread covers (row lm, k-half lh)
    int lm = tid >> 1, lh = tid & 1;
    const float* aP  = A + (size_t)srows[lm] * K + lh * 16;
    const __half* bhP = Whi + (size_t)e * wStride + (size_t)(nBase + lm) * K + lh * 16;
    const __half* bmP = Wmd + (size_t)e * wStride + (size_t)(nBase + lm) * K + lh * 16;
    uint32_t su0 = (uint32_t)(lm * 64 + (((lh * 2 + 0) ^ (lm & 3)) << 4));
    uint32_t su1 = (uint32_t)(lm * 64 + (((lh * 2 + 1) ^ (lm & 3)) << 4));

    // warp tiling: wm in {0,1} (64 rows), wn in {0..3} (32 cols)
    int wm = wid & 1, wn = wid >> 1;
    // ldmatrix lane geometry
    int a_r = (lane & 7) + ((lane & 8) ? 8 : 0);    // row within m16
    int a_u = (lane >> 4) & 1;                      // k-unit within k16
    int b_r = (lane & 7) + ((lane & 16) ? 8 : 0);   // row within n16
    int b_u = (lane >> 3) & 1;

    float acc1[4][4][4], acc2[4][4][4];
#pragma unroll
    for (int i = 0; i < 4; ++i)
#pragma unroll
        for (int j = 0; j < 4; ++j)
#pragma unroll
            for (int q = 0; q < 4; ++q) { acc1[i][j][q] = 0.f; acc2[i][j][q] = 0.f; }

    int nChunks = K >> 5;

    float4 fa[4];       // A fetch regs (16 floats)
    uint4  fbh[2], fbm[2];

    // ---- prologue: fetch + STS chunk 0 ----
#pragma unroll
    for (int j = 0; j < 4; ++j) fa[j] = *(const float4*)(aP + j * 4);
    fbh[0] = *(const uint4*)(bhP);     fbh[1] = *(const uint4*)(bhP + 8);
    fbm[0] = *(const uint4*)(bmP);     fbm[1] = *(const uint4*)(bmP + 8);
    {
        uint32_t hw[8], mw[8];
#pragma unroll
        for (int j = 0; j < 4; ++j) {
            __half h0, m0, h1, m1, h2, m2, h3, m3;
            split2(fa[j].x, h0, m0); split2(fa[j].y, h1, m1);
            split2(fa[j].z, h2, m2); split2(fa[j].w, h3, m3);
            hw[j * 2] = packh(h0, h1); hw[j * 2 + 1] = packh(h2, h3);
            mw[j * 2] = packh(m0, m1); mw[j * 2 + 1] = packh(m2, m3);
        }
        uint32_t base = sb + STG_BASE;
        asm volatile("st.shared.v4.b32 [%0], {%1,%2,%3,%4};" :: "r"(base + su0), "r"(hw[0]), "r"(hw[1]), "r"(hw[2]), "r"(hw[3]) : "memory");
        asm volatile("st.shared.v4.b32 [%0], {%1,%2,%3,%4};" :: "r"(base + su1), "r"(hw[4]), "r"(hw[5]), "r"(hw[6]), "r"(hw[7]) : "memory");
        asm volatile("st.shared.v4.b32 [%0], {%1,%2,%3,%4};" :: "r"(base + 8192 + su0), "r"(mw[0]), "r"(mw[1]), "r"(mw[2]), "r"(mw[3]) : "memory");
        asm volatile("st.shared.v4.b32 [%0], {%1,%2,%3,%4};" :: "r"(base + 8192 + su1), "r"(mw[4]), "r"(mw[5]), "r"(mw[6]), "r"(mw[7]) : "memory");
        asm volatile("st.shared.v4.b32 [%0], {%1,%2,%3,%4};" :: "r"(base + 16384 + su0), "r"(fbh[0].x), "r"(fbh[0].y), "r"(fbh[0].z), "r"(fbh[0].w) : "memory");
        asm volatile("st.shared.v4.b32 [%0], {%1,%2,%3,%4};" :: "r"(base + 16384 + su1), "r"(fbh[1].x), "r"(fbh[1].y), "r"(fbh[1].z), "r"(fbh[1].w) : "memory");
        asm volatile("st.shared.v4.b32 [%0], {%1,%2,%3,%4};" :: "r"(base + 24576 + su0), "r"(fbm[0].x), "r"(fbm[0].y), "r"(fbm[0].z), "r"(fbm[0].w) : "memory");
        asm volatile("st.shared.v4.b32 [%0], {%1,%2,%3,%4};" :: "r"(base + 24576 + su1), "r"(fbm[1].x), "r"(fbm[1].y), "r"(fbm[1].z), "r"(fbm[1].w) : "memory");
    }
    __syncthreads();

    for (int c = 0; c < nChunks; ++c) {
        int s = c & 1;
        uint32_t stage = sb + STG_BASE + s * STG_SZ;
        // fetch chunk c+1
        if (c + 1 < nChunks) {
            int k0 = (c + 1) << 5;
#pragma unroll
            for (int j = 0; j < 4; ++j) fa[j] = *(const float4*)(aP + k0 + j * 4);
            fbh[0] = *(const uint4*)(bhP + k0);  fbh[1] = *(const uint4*)(bhP + k0 + 8);
            fbm[0] = *(const uint4*)(bmP + k0);  fbm[1] = *(const uint4*)(bmP + k0 + 8);
        }
        // compute on stage s
#pragma unroll
        for (int ks = 0; ks < 2; ++ks) {
            uint32_t ah[4][4], am[4][4], bh[4][2], bm[4][2];
#pragma unroll
            for (int ma = 0; ma < 4; ++ma) {
                int row = wm * 64 + ma * 16 + a_r;
                uint32_t addr = stage + row * 64 + ((((ks << 1) + a_u) ^ (row & 3)) << 4);
                LDSM_X4(ah[ma][0], ah[ma][1], ah[ma][2], ah[ma][3], addr);
                LDSM_X4(am[ma][0], am[ma][1], am[ma][2], am[ma][3], addr + 8192);
            }
#pragma unroll
            for (int ng = 0; ng < 2; ++ng) {
                int row = wn * 32 + ng * 16 + b_r;
                uint32_t addr = stage + 16384 + row * 64 + ((((ks << 1) + b_u) ^ (row & 3)) << 4);
                LDSM_X4(bh[ng * 2][0], bh[ng * 2][1], bh[ng * 2 + 1][0], bh[ng * 2 + 1][1], addr);
                LDSM_X4(bm[ng * 2][0], bm[ng * 2][1], bm[ng * 2 + 1][0], bm[ng * 2 + 1][1], addr + 8192);
            }
#pragma unroll
            for (int ma = 0; ma < 4; ++ma)
#pragma unroll
                for (int nb = 0; nb < 4; ++nb) {
                    MMA16816(acc1[ma][nb], ah[ma], bh[nb]);
                    MMA16816(acc2[ma][nb], ah[ma], bm[nb]);
                    MMA16816(acc2[ma][nb], am[ma], bh[nb]);
                }
        }
        // STS chunk c+1 into other stage
        if (c + 1 < nChunks) {
            uint32_t base = sb + STG_BASE + (s ^ 1) * STG_SZ;
            uint32_t hw[8], mw[8];
#pragma unroll
            for (int j = 0; j < 4; ++j) {
                __half h0, m0, h1, m1, h2, m2, h3, m3;
                split2(fa[j].x, h0, m0); split2(fa[j].y, h1, m1);
                split2(fa[j].z, h2, m2); split2(fa[j].w, h3, m3);
                hw[j * 2] = packh(h0, h1); hw[j * 2 + 1] = packh(h2, h3);
                mw[j * 2] = packh(m0, m1); mw[j * 2 + 1] = packh(m2, m3);
            }
            asm volatile("st.shared.v4.b32 [%0], {%1,%2,%3,%4};" :: "r"(base + su0), "r"(hw[0]), "r"(hw[1]), "r"(hw[2]), "r"(hw[3]) : "memory");
            asm volatile("st.shared.v4.b32 [%0], {%1,%2,%3,%4};" :: "r"(base + su1), "r"(hw[4]), "r"(hw[5]), "r"(hw[6]), "r"(hw[7]) : "memory");
            asm volatile("st.shared.v4.b32 [%0], {%1,%2,%3,%4};" :: "r"(base + 8192 + su0), "r"(mw[0]), "r"(mw[1]), "r"(mw[2]), "r"(mw[3]) : "memory");
            asm volatile("st.shared.v4.b32 [%0], {%1,%2,%3,%4};" :: "r"(base + 8192 + su1), "r"(mw[4]), "r"(mw[5]), "r"(mw[6]), "r"(mw[7]) : "memory");
            asm volatile("st.shared.v4.b32 [%0], {%1,%2,%3,%4};" :: "r"(base + 16384 + su0), "r"(fbh[0].x), "r"(fbh[0].y), "r"(fbh[0].z), "r"(fbh[0].w) : "memory");
            asm volatile("st.shared.v4.b32 [%0], {%1,%2,%3,%4};" :: "r"(base + 16384 + su1), "r"(fbh[1].x), "r"(fbh[1].y), "r"(fbh[1].z), "r"(fbh[1].w) : "memory");
            asm volatile("st.shared.v4.b32 [%0], {%1,%2,%3,%4};" :: "r"(base + 24576 + su0), "r"(fbm[0].x), "r"(fbm[0].y), "r"(fbm[0].z), "r"(fbm[0].w) : "memory");
            asm volatile("st.shared.v4.b32 [%0], {%1,%2,%3,%4};" :: "r"(base + 24576 + su1), "r"(fbm[1].x), "r"(fbm[1].y), "r"(fbm[1].z), "r"(fbm[1].w) : "memory");
        }
        __syncthreads();
    }

    // ---- epilogue: combine splits, bias, relu, scatter-store ----
#pragma unroll
    for (int nb = 0; nb < 4; ++nb) {
        int col = nBase + wn * 32 + nb * 8 + (lane & 3) * 2;
        float b0 = __ldg(&bias[(size_t)e * bStride + col]);
        float b1 = __ldg(&bias[(size_t)e * bStride + col + 1]);
#pragma unroll
        for (int ma = 0; ma < 4; ++ma) {
            int rl0 = wm * 64 + ma * 16 + (lane >> 2);
            int rl1 = rl0 + 8;
            float v00 = acc1[ma][nb][0] + acc2[ma][nb][0] * IMIDSC + b0;
            float v01 = acc1[ma][nb][1] + acc2[ma][nb][1] * IMIDSC + b1;
            float v10 = acc1[ma][nb][2] + acc2[ma][nb][2] * IMIDSC + b0;
            float v11 = acc1[ma][nb][3] + acc2[ma][nb][3] * IMIDSC + b1;
            if (doRelu) {
                v00 = fmaxf(v00, 0.f); v01 = fmaxf(v01, 0.f);
                v10 = fmaxf(v10, 0.f); v11 = fmaxf(v11, 0.f);
            }
            if (mBase + rl0 < M) {
                int orow = scatter ? srows[rl0] : mBase + rl0;
                *(float2*)&Cout[(size_t)orow * N + col] = make_float2(v00, v01);
            }
            if (mBase + rl1 < M) {
                int orow = scatter ? srows[rl1] : mBase + rl1;
                *(float2*)&Cout[(size_t)orow * N + col] = make_float2(v10, v11);
            }
        }
    }
}

// ================= router logits + argmax + dispatch/compaction =================
__global__ __launch_bounds__(128) void dispatch_kernel(
    const float* __restrict__ hidden, const float* __restrict__ W2,
    const float* __restrict__ b2,
    const int* __restrict__ curList, const int* __restrict__ curCnt,
    int* __restrict__ nextList, int* __restrict__ nextCnt,
    int* __restrict__ expertList, int* __restrict__ expertCnt,
    int* __restrict__ actOut)
{
    int i = blockIdx.x;
    if (i >= *curCnt) return;
    int tid = threadIdx.x;

    __shared__ float sW2[ND * (NEXP + 1)];
    __shared__ float sred[4][NEXP + 1];
    for (int idx = tid; idx < ND * (NEXP + 1); idx += 128) sW2[idx] = W2[idx];
    __syncthreads();

    float acc[NEXP + 1];
#pragma unroll
    for (int j = 0; j <= NEXP; ++j) acc[j] = 0.f;

    const float* hr = hidden + (size_t)i * ND;
    for (int k = tid; k < ND; k += 128) {
        float hv = hr[k];
#pragma unroll
        for (int j = 0; j <= NEXP; ++j) acc[j] += hv * sW2[k * (NEXP + 1) + j];
    }
#pragma unroll
    for (int j = 0; j <= NEXP; ++j)
        for (int o = 16; o; o >>= 1) acc[j] += __shfl_xor_sync(0xffffffffu, acc[j], o);
    int warp = tid >> 5, lane = tid & 31;
    if (lane == 0)
#pragma unroll
        for (int j = 0; j <= NEXP; ++j) sred[warp][j] = acc[j];
    __syncthreads();

    if (tid == 0) {
        float best = -FLT_MAX; int bi = 0;
#pragma unroll
        for (int j = 0; j <= NEXP; ++j) {
            float v = sred[0][j] + sred[1][j] + sred[2][j] + sred[3][j] + b2[j];
            if (v > best) { best = v; bi = j; }
        }
        if (bi < NEXP) {
            int sample = curList[i];
            int p = atomicAdd(&expertCnt[bi], 1);
            expertList[bi * NB + p] = sample;
            int q = atomicAdd(nextCnt, 1);
            nextList[q] = sample;
            actOut[sample] = bi;
        }
    }
}

// ================= LayerNorm + residual into h =================
__global__ __launch_bounds__(256) void ln_kernel(
    const float* __restrict__ z2, float* __restrict__ h,
    const float* __restrict__ g, const float* __restrict__ beta,
    const int* __restrict__ nextList, const int* __restrict__ nextCnt,
    const int* __restrict__ actSel)
{
    int j = blockIdx.x;
    if (j >= *nextCnt) return;
    int sample = nextList[j];
    int e = actSel[sample];
    int tid = threadIdx.x;

    const float4 x = *(const float4*)&z2[(size_t)sample * ND + tid * 4];

    __shared__ float red[8];
    __shared__ float bc;
    int warp = tid >> 5, lane = tid & 31;

    float s = x.x + x.y + x.z + x.w;
    for (int o = 16; o; o >>= 1) s += __shfl_xor_sync(0xffffffffu, s, o);
    if (lane == 0) red[warp] = s;
    __syncthreads();
    if (tid == 0) {
        float t = 0.f;
        for (int w = 0; w < 8; ++w) t += red[w];
        bc = t * (1.f / ND);
    }
    __syncthreads();
    float mean = bc;
    __syncthreads();

    float d0 = x.x - mean, d1 = x.y - mean, d2 = x.z - mean, d3 = x.w - mean;
    float ss = d0 * d0 + d1 * d1 + d2 * d2 + d3 * d3;
    for (int o = 16; o; o >>= 1) ss += __shfl_xor_sync(0xffffffffu, ss, o);
    if (lane == 0) red[warp] = ss;
    __syncthreads();
    if (tid == 0) {
        float t = 0.f;
        for (int w = 0; w < 8; ++w) t += red[w];
        bc = t * (1.f / ND);
    }
    __syncthreads();
    float rstd = rsqrtf(bc + LNEPS);

    float4 hv = *(const float4*)&h[(size_t)sample * ND + tid * 4];
    float4 gg = *(const float4*)&g[(size_t)e * ND + tid * 4];
    float4 bt = *(const float4*)&beta[(size_t)e * ND + tid * 4];
    float4 o;
    o.x = hv.x + d0 * rstd * gg.x + bt.x;
    o.y = hv.y + d1 * rstd * gg.y + bt.y;
    o.z = hv.z + d2 * rstd * gg.z + bt.z;
    o.w = hv.w + d3 * rstd * gg.w + bt.w;
    *(float4*)&h[(size_t)sample * ND + tid * 4] = o;
}

// ================= output head =================
__global__ __launch_bounds__(256) void head_kernel(
    const float* __restrict__ h, const float* __restrict__ oW,
    const float* __restrict__ ob, float* __restrict__ out)
{
    int b = blockIdx.x, tid = threadIdx.x;
    float acc[NC];
#pragma unroll
    for (int j = 0; j < NC; ++j) acc[j] = 0.f;

    const float* hr = h + (size_t)b * ND;
    for (int k = tid; k < ND; k += 256) {
        float hv = hr[k];
#pragma unroll
        for (int j = 0; j < NC; ++j) acc[j] += hv * oW[k * NC + j];
    }
#pragma unroll
    for (int j = 0; j < NC; ++j)
        for (int o = 16; o; o >>= 1) acc[j] += __shfl_xor_sync(0xffffffffu, acc[j], o);

    __shared__ float sred[8][NC];
    int warp = tid >> 5, lane = tid & 31;
    if (lane == 0)
#pragma unroll
        for (int j = 0; j < NC; ++j) sred[warp][j] = acc[j];
    __syncthreads();
    if (tid < NC) {
        float t = 0.f;
        for (int w = 0; w < 8; ++w) t += sred[w][tid];
        out[b * NC + tid] = t + ob[tid];
    }
}

// ================= launch =================
extern "C" void kernel_launch(void* const* d_in, const int* in_sizes, int n_in,
                              void* d_out, int out_size)
{
    const int*   ids = (const int*)d_in[0];
    const float* emb = (const float*)d_in[1];
    const float* rW1 = (const float*)d_in[2];
    const float* rb1 = (const float*)d_in[3];
    const float* rW2 = (const float*)d_in[4];
    const float* rb2 = (const float*)d_in[5];
    const float* eW1 = (const float*)d_in[6];
    const float* eb1 = (const float*)d_in[7];
    const float* eW2 = (const float*)d_in[8];
    const float* eb2 = (const float*)d_in[9];
    const float* eg  = (const float*)d_in[10];
    const float* ebt = (const float*)d_in[11];
    const float* oW  = (const float*)d_in[12];
    const float* ob  = (const float*)d_in[13];
    float* out = (float*)d_out;

    void* p;
    cudaGetSymbolAddress(&p, g_h);      float* h      = (float*)p;
    cudaGetSymbolAddress(&p, g_hidden); float* hidden = (float*)p;
    cudaGetSymbolAddress(&p, g_z1);     float* z1     = (float*)p;
    cudaGetSymbolAddress(&p, g_z2);     float* z2     = (float*)p;
    cudaGetSymbolAddress(&p, g_listA);  int* listA    = (int*)p;
    cudaGetSymbolAddress(&p, g_listB);  int* listB    = (int*)p;
    cudaGetSymbolAddress(&p, g_elist);  int* elist    = (int*)p;
    cudaGetSymbolAddress(&p, g_actsel); int* actsel   = (int*)p;
    cudaGetSymbolAddress(&p, g_cnt);    int* cnt      = (int*)p;
    cudaGetSymbolAddress(&p, g_wbuf);   __half* wbuf  = (__half*)p;

    cudaFuncSetAttribute(hmma_gemm_kernel, cudaFuncAttributeMaxDynamicSharedMemorySize, HG_SMEM);

    // weight transpose + fp16x2 split (idempotent each call)
    {
        dim3 blk(32, 8);
        convT_kernel<<<dim3(ND / 32, ND / 32, 1), blk>>>(
            rW1, wbuf + WB_RW1, wbuf + WB_RW1 + S_RW1, ND, ND);
        convT_kernel<<<dim3(NH / 32, ND / 32, NEXP), blk>>>(
            eW1, wbuf + WB_EW1, wbuf + WB_EW1 + S_EW1, ND, NH);
        convT_kernel<<<dim3(ND / 32, NH / 32, NEXP), blk>>>(
            eW2, wbuf + WB_EW2, wbuf + WB_EW2 + S_EW2, NH, ND);
    }

    init_kernel<<<8, 256>>>(listA, cnt);
    embed_kernel<<<NB, 256>>>(ids, emb, h);

    for (int step = 0; step < NSTEPS; ++step) {
        int* curList = (step & 1) ? listB : listA;
        int* nxtList = (step & 1) ? listA : listB;
        int* curCnt  = cnt + (step & 1);
        int* nxtCnt  = cnt + ((step + 1) & 1);
        int* eCnt    = cnt + 8;

        reset_kernel<<<1, 32>>>(nxtCnt, eCnt);

        // router layer 1: hidden = relu(h[cur] @ rW1 + rb1), compact rows
        hmma_gemm_kernel<<<dim3(NB / 128, ND / 128, 1), 256, HG_SMEM>>>(
            h, wbuf + WB_RW1, wbuf + WB_RW1 + S_RW1,
            rb1, hidden, curList, curCnt,
            ND, ND, 1, 0, (size_t)0, 0, 0);

        dispatch_kernel<<<NB, 128>>>(hidden, rW2, rb2, curList, curCnt,
                                     nxtList, nxtCnt, elist, eCnt, actsel);

        // expert layer 1: z1[s] = relu(h[s] @ eW1[e] + eb1[e])
        hmma_gemm_kernel<<<dim3(NB / 128, NH / 128, NEXP), 256, HG_SMEM>>>(
            h, wbuf + WB_EW1, wbuf + WB_EW1 + S_EW1,
            eb1, z1, elist, eCnt,
            ND, NH, 1, 1, (size_t)ND * NH, NH, NB);

        // expert layer 2: z2[s] = z1[s] @ eW2[e] + eb2[e]
        hmma_gemm_kernel<<<dim3(NB / 128, ND / 128, NEXP), 256, HG_SMEM>>>(
            z1, wbuf + WB_EW2, wbuf + WB_EW2 + S_EW2,
            eb2, z2, elist, eCnt,
            NH, ND, 0, 1, (size_t)NH * ND, ND, NB);

        ln_kernel<<<NB, 256>>>(z2, h, eg, ebt, nxtList, nxtCnt, actsel);
    }

    head_kernel<<<NB, 256>>>(h, oW, ob, out);
}